// round 3
// baseline (speedup 1.0000x reference)
#include <cuda_runtime.h>
#include <math.h>

#define NN 20000
#define EE 320000
#define IND 128
#define HH 8
#define CC 128
#define HCD 1024
#define GG 64
#define NEG_SLOPE 0.2f

// ---------------- scratch (static device globals; no allocation) ----------------
__device__ float g_xl[(size_t)NN * HCD];      // x@Wl+bl        (~82 MB)
__device__ float g_xr[(size_t)NN * HCD];      // x@Wr+br        (~82 MB)
__device__ float g_out[(size_t)NN * HCD];     // residual, then +aggregate (~82 MB)
__device__ float g_ebuf[(size_t)EE * HH];     // per-edge logits (10 MB)
__device__ float g_h[(size_t)NN * CC];        // ELU(Linear)    (10 MB)
__device__ int   g_deg[NN];
__device__ int   g_rowptr[NN + 1];
__device__ int   g_cursor[NN];
__device__ int   g_adj[EE];
__device__ float g_pooled[GG * CC];
__device__ float g_cnt[GG];

// ---------------- small utility kernels ----------------
__global__ void init_k() {
    int idx = blockIdx.x * 256 + threadIdx.x;
    if (idx < NN) g_deg[idx] = 0;
    if (idx < GG * CC) g_pooled[idx] = 0.f;
    if (idx < GG) g_cnt[idx] = 0.f;
}

__global__ void deg_k(const int* __restrict__ ei) {
    int e = blockIdx.x * 256 + threadIdx.x;
    if (e < EE) {
        int dst = ei[EE + e];
        atomicAdd(&g_deg[dst], 1);
    }
}

// single-block exclusive scan over g_deg -> g_rowptr, g_cursor
__global__ void scan_k() {
    __shared__ int s[1024];
    __shared__ int carry;
    int tid = threadIdx.x;
    if (tid == 0) carry = 0;
    __syncthreads();
    for (int base = 0; base < NN; base += 1024) {
        int idx = base + tid;
        int v = (idx < NN) ? g_deg[idx] : 0;
        s[tid] = v;
        __syncthreads();
        for (int off = 1; off < 1024; off <<= 1) {
            int t = (tid >= off) ? s[tid - off] : 0;
            __syncthreads();
            s[tid] += t;
            __syncthreads();
        }
        int incl = s[tid];
        int c = carry;
        __syncthreads();
        if (tid == 1023) carry = c + incl;
        if (idx < NN) {
            int ex = c + incl - v;
            g_rowptr[idx] = ex;
            g_cursor[idx] = ex;
        }
        __syncthreads();
    }
    if (tid == 0) g_rowptr[NN] = carry;
}

__global__ void adj_k(const int* __restrict__ ei) {
    int e = blockIdx.x * 256 + threadIdx.x;
    if (e < EE) {
        int dst = ei[EE + e];
        int pos = atomicAdd(&g_cursor[dst], 1);
        g_adj[pos] = e;
    }
}

// ---------------- tiled fp32 GEMM: Out[M,Nd] = act(X[M,K] @ W[K,Nd] + bias) ----------------
__device__ __forceinline__ float* dest_ptr(int sel) {
    switch (sel) {
        case 0: return g_xl;
        case 1: return g_xr;
        case 2: return g_out;
        default: return g_h;
    }
}

__global__ void gemm_k(const float* __restrict__ Xp, int x_is_gout,
                       const float* __restrict__ W, const float* __restrict__ bias,
                       int dest_sel, int M, int K, int Nd, int act) {
    __shared__ __align__(16) float s_a[16][68];
    __shared__ __align__(16) float s_b[16][64];
    const float* X = x_is_gout ? g_out : Xp;
    float* Out = dest_ptr(dest_sel);

    int tid = threadIdx.x;
    int tx = tid & 15, ty = tid >> 4;
    int rowBase = blockIdx.y * 64, colBase = blockIdx.x * 64;
    int aRow = tid >> 2, aC4 = tid & 3;
    int bRow = tid >> 4, bC4 = tid & 15;

    float acc[4][4];
#pragma unroll
    for (int i = 0; i < 4; i++)
#pragma unroll
        for (int j = 0; j < 4; j++) acc[i][j] = 0.f;

    for (int kb = 0; kb < K; kb += 16) {
        float4 av = make_float4(0.f, 0.f, 0.f, 0.f);
        int gr = rowBase + aRow;
        if (gr < M) av = *(const float4*)&X[(size_t)gr * K + kb + aC4 * 4];
        s_a[aC4 * 4 + 0][aRow] = av.x;
        s_a[aC4 * 4 + 1][aRow] = av.y;
        s_a[aC4 * 4 + 2][aRow] = av.z;
        s_a[aC4 * 4 + 3][aRow] = av.w;
        float4 bv = *(const float4*)&W[(size_t)(kb + bRow) * Nd + colBase + bC4 * 4];
        *(float4*)&s_b[bRow][bC4 * 4] = bv;
        __syncthreads();
#pragma unroll
        for (int k = 0; k < 16; k++) {
            float ra[4], rb[4];
#pragma unroll
            for (int i = 0; i < 4; i++) ra[i] = s_a[k][ty * 4 + i];
#pragma unroll
            for (int j = 0; j < 4; j++) rb[j] = s_b[k][tx * 4 + j];
#pragma unroll
            for (int i = 0; i < 4; i++)
#pragma unroll
                for (int j = 0; j < 4; j++) acc[i][j] += ra[i] * rb[j];
        }
        __syncthreads();
    }

    float4 bb = *(const float4*)&bias[colBase + tx * 4];
#pragma unroll
    for (int i = 0; i < 4; i++) {
        int gr = rowBase + ty * 4 + i;
        if (gr < M) {
            float v0 = acc[i][0] + bb.x;
            float v1 = acc[i][1] + bb.y;
            float v2 = acc[i][2] + bb.z;
            float v3 = acc[i][3] + bb.w;
            if (act) {  // ELU
                v0 = v0 > 0.f ? v0 : (__expf(v0) - 1.f);
                v1 = v1 > 0.f ? v1 : (__expf(v1) - 1.f);
                v2 = v2 > 0.f ? v2 : (__expf(v2) - 1.f);
                v3 = v3 > 0.f ? v3 : (__expf(v3) - 1.f);
            }
            *(float4*)&Out[(size_t)gr * Nd + colBase + tx * 4] = make_float4(v0, v1, v2, v3);
        }
    }
}

// ---------------- per-edge GATv2 logits: e[e,h] = sum_c att[h,c]*lrelu(xl[src]+xr[dst]) ----------------
__global__ void edge_logits_k(const int* __restrict__ ei, const float* __restrict__ att) {
    __shared__ float4 s_att[256];
    int tid = threadIdx.x;
    s_att[tid] = ((const float4*)att)[tid];
    __syncthreads();

    int e = blockIdx.x * 8 + (tid >> 5);
    int lane = tid & 31;
    if (e >= EE) return;
    size_t src = (size_t)ei[e];
    size_t dst = (size_t)ei[EE + e];
    const float4* A = (const float4*)&g_xl[src * HCD];
    const float4* B = (const float4*)&g_xr[dst * HCD];

    float acc[8];
#pragma unroll
    for (int it = 0; it < 8; it++) {
        int j = it * 32 + lane;  // head = it, channel = (lane)*4 within head
        float4 a = A[j], b = B[j], w = s_att[j];
        float vx = a.x + b.x, vy = a.y + b.y, vz = a.z + b.z, vw = a.w + b.w;
        vx = vx > 0.f ? vx : NEG_SLOPE * vx;
        vy = vy > 0.f ? vy : NEG_SLOPE * vy;
        vz = vz > 0.f ? vz : NEG_SLOPE * vz;
        vw = vw > 0.f ? vw : NEG_SLOPE * vw;
        acc[it] = vx * w.x + vy * w.y + vz * w.z + vw * w.w;
    }
#pragma unroll
    for (int it = 0; it < 8; it++) {
        float v = acc[it];
#pragma unroll
        for (int off = 16; off > 0; off >>= 1) v += __shfl_xor_sync(0xffffffffu, v, off);
        acc[it] = v;
    }
    if (lane == 0) {
#pragma unroll
        for (int h = 0; h < 8; h++) g_ebuf[(size_t)e * 8 + h] = acc[h];
    }
}

// ---------------- per-node segment softmax + weighted aggregate (gather, no atomics) ----------------
#define CHK 128
__global__ void node_aggregate_k(const int* __restrict__ ei) {
    int i = blockIdx.x;
    int beg = g_rowptr[i], end = g_rowptr[i + 1];
    int tid = threadIdx.x, lane = tid & 31, wid = tid >> 5;

    __shared__ float s_m[8], s_inv[8];
    __shared__ int s_src[CHK];
    __shared__ float s_alpha[CHK][9];  // pad to 9 to de-conflict

    // warp `wid` computes max & exp-sum for head `wid`
    float m = -3.4e38f;
    for (int k = beg + lane; k < end; k += 32)
        m = fmaxf(m, g_ebuf[(size_t)g_adj[k] * 8 + wid]);
#pragma unroll
    for (int off = 16; off > 0; off >>= 1) m = fmaxf(m, __shfl_xor_sync(0xffffffffu, m, off));
    float ssum = 0.f;
    for (int k = beg + lane; k < end; k += 32)
        ssum += __expf(g_ebuf[(size_t)g_adj[k] * 8 + wid] - m);
#pragma unroll
    for (int off = 16; off > 0; off >>= 1) ssum += __shfl_xor_sync(0xffffffffu, ssum, off);
    if (lane == 0) {
        s_m[wid] = m;
        s_inv[wid] = ssum > 0.f ? 1.f / ssum : 0.f;
    }
    __syncthreads();

    float4 acc = make_float4(0.f, 0.f, 0.f, 0.f);
    int h = tid >> 5;  // 256 threads * float4 = 1024 channels; head = tid/32

    for (int cb = beg; cb < end; cb += CHK) {
        int cnt = min(CHK, end - cb);
        if (tid < cnt) {
            int eid = g_adj[cb + tid];
            s_src[tid] = ei[eid];
#pragma unroll
            for (int hh = 0; hh < 8; hh++)
                s_alpha[tid][hh] = __expf(g_ebuf[(size_t)eid * 8 + hh] - s_m[hh]) * s_inv[hh];
        }
        __syncthreads();
        for (int k = 0; k < cnt; k++) {
            const float4* xa = (const float4*)&g_xl[(size_t)s_src[k] * HCD];
            float a = s_alpha[k][h];
            float4 v = xa[tid];
            acc.x += a * v.x;
            acc.y += a * v.y;
            acc.z += a * v.z;
            acc.w += a * v.w;
        }
        __syncthreads();
    }

    float4* o = (float4*)&g_out[(size_t)i * HCD];
    float4 r = o[tid];
    o[tid] = make_float4(r.x + acc.x, r.y + acc.y, r.z + acc.z, r.w + acc.w);
}

// ---------------- global mean pool ----------------
__global__ void pool_k(const int* __restrict__ batch) {
    int idx = blockIdx.x * 256 + threadIdx.x;
    if (idx < NN * CC) {
        int n = idx >> 7, c = idx & 127;
        int g = batch[n];
        atomicAdd(&g_pooled[g * CC + c], g_h[idx]);
        if (c == 0) atomicAdd(&g_cnt[g], 1.0f);
    }
}

// ---------------- MLP head: 128->16->32->5 ----------------
__global__ void head_k(const float* __restrict__ W1, const float* __restrict__ b1,
                       const float* __restrict__ W2, const float* __restrict__ b2,
                       const float* __restrict__ W3, const float* __restrict__ b3,
                       float* __restrict__ out) {
    __shared__ float sp[GG][CC];   // 32 KB
    __shared__ float h1[GG][16];
    __shared__ float h2[GG][32];
    int tid = threadIdx.x;
    for (int idx = tid; idx < GG * CC; idx += 256) {
        int g = idx >> 7;
        float c = g_cnt[g];
        c = c < 1.f ? 1.f : c;
        sp[g][idx & 127] = g_pooled[idx] / c;
    }
    __syncthreads();
    for (int idx = tid; idx < GG * 16; idx += 256) {
        int g = idx / 16, o = idx % 16;
        float s = b1[o];
        for (int k = 0; k < CC; k++) s += sp[g][k] * W1[k * 16 + o];
        h1[g][o] = s > 0.f ? s : 0.f;
    }
    __syncthreads();
    for (int idx = tid; idx < GG * 32; idx += 256) {
        int g = idx / 32, o = idx % 32;
        float s = b2[o];
        for (int k = 0; k < 16; k++) s += h1[g][k] * W2[k * 32 + o];
        h2[g][o] = s > 0.f ? s : 0.f;
    }
    __syncthreads();
    for (int idx = tid; idx < GG * 5; idx += 256) {
        int g = idx / 5, o = idx % 5;
        float s = b3[o];
        for (int k = 0; k < 32; k++) s += h2[g][k] * W3[k * 5 + o];
        out[idx] = s;
    }
}

// ---------------- launch ----------------
extern "C" void kernel_launch(void* const* d_in, const int* in_sizes, int n_in,
                              void* d_out, int out_size) {
    const float* x = (const float*)d_in[0];
    const int* ei = (const int*)d_in[1];
    const int* batch = (const int*)d_in[2];
    const float* Wl = (const float*)d_in[3];
    const float* bl = (const float*)d_in[4];
    const float* Wr = (const float*)d_in[5];
    const float* br = (const float*)d_in[6];
    const float* att = (const float*)d_in[7];
    const float* Wres = (const float*)d_in[8];
    const float* bias_attn = (const float*)d_in[9];
    const float* W_lin = (const float*)d_in[10];
    const float* b_lin = (const float*)d_in[11];
    const float* W1 = (const float*)d_in[12];
    const float* b1 = (const float*)d_in[13];
    const float* W2 = (const float*)d_in[14];
    const float* b2 = (const float*)d_in[15];
    const float* W3 = (const float*)d_in[16];
    const float* b3 = (const float*)d_in[17];
    float* out = (float*)d_out;

    // CSR build
    init_k<<<(NN + 255) / 256, 256>>>();
    deg_k<<<(EE + 255) / 256, 256>>>(ei);
    scan_k<<<1, 1024>>>();
    adj_k<<<(EE + 255) / 256, 256>>>(ei);

    // dense transforms
    dim3 blk(256);
    dim3 g1(HCD / 64, (NN + 63) / 64);
    gemm_k<<<g1, blk>>>(x, 0, Wl, bl, /*dest*/ 0, NN, IND, HCD, 0);          // xl
    gemm_k<<<g1, blk>>>(x, 0, Wr, br, /*dest*/ 1, NN, IND, HCD, 0);          // xr
    gemm_k<<<g1, blk>>>(x, 0, Wres, bias_attn, /*dest*/ 2, NN, IND, HCD, 0); // residual pre-fill

    // GATv2 attention
    edge_logits_k<<<(EE + 7) / 8, 256>>>(ei, att);
    node_aggregate_k<<<NN, 256>>>(ei);

    // Linear + ELU
    dim3 g2(CC / 64, (NN + 63) / 64);
    gemm_k<<<g2, blk>>>(nullptr, 1, W_lin, b_lin, /*dest*/ 3, NN, HCD, CC, 1);

    // pool + head
    pool_k<<<(NN * CC + 255) / 256, 256>>>(batch);
    head_k<<<1, 256>>>(W1, b1, W2, b2, W3, b3, out);
}

// round 4
// speedup vs baseline: 1.4798x; 1.4798x over previous
#include <cuda_runtime.h>
#include <cuda_bf16.h>
#include <math.h>
#include <stdint.h>

#define NN 20000
#define EE 320000
#define IND 128
#define HH 8
#define CC 128
#define HCD 1024
#define GG 64
#define NEG_SLOPE 0.2f

// ---------------- scratch (static device globals; no allocation) ----------------
__device__ __nv_bfloat16 g_xl_bf[(size_t)NN * HCD];  // x@Wl+bl  (41 MB, bf16)
__device__ __nv_bfloat16 g_xr_bf[(size_t)NN * HCD];  // x@Wr+br  (41 MB, bf16)
__device__ float g_out[(size_t)NN * HCD];            // residual, then +aggregate (82 MB)
__device__ float g_ebuf[(size_t)EE * HH];            // per-edge logits (10 MB)
__device__ float g_h[(size_t)NN * CC];               // ELU(Linear) (10 MB)
__device__ int   g_deg[NN];
__device__ int   g_rowptr[NN + 1];
__device__ int   g_cursor[NN];
__device__ int   g_adj[EE];
__device__ float g_pooled[GG * CC];

// ---------------- small utility kernels ----------------
__global__ void init_k() {
    int idx = blockIdx.x * 256 + threadIdx.x;
    if (idx < NN) g_deg[idx] = 0;
}

__global__ void deg_k(const int* __restrict__ ei) {
    int e = blockIdx.x * 256 + threadIdx.x;
    if (e < EE) atomicAdd(&g_deg[ei[EE + e]], 1);
}

__global__ void scan_k() {
    __shared__ int s[1024];
    __shared__ int carry;
    int tid = threadIdx.x;
    if (tid == 0) carry = 0;
    __syncthreads();
    for (int base = 0; base < NN; base += 1024) {
        int idx = base + tid;
        int v = (idx < NN) ? g_deg[idx] : 0;
        s[tid] = v;
        __syncthreads();
        for (int off = 1; off < 1024; off <<= 1) {
            int t = (tid >= off) ? s[tid - off] : 0;
            __syncthreads();
            s[tid] += t;
            __syncthreads();
        }
        int incl = s[tid];
        int c = carry;
        __syncthreads();
        if (tid == 1023) carry = c + incl;
        if (idx < NN) {
            int ex = c + incl - v;
            g_rowptr[idx] = ex;
            g_cursor[idx] = ex;
        }
        __syncthreads();
    }
    if (tid == 0) g_rowptr[NN] = carry;
}

__global__ void adj_k(const int* __restrict__ ei) {
    int e = blockIdx.x * 256 + threadIdx.x;
    if (e < EE) {
        int pos = atomicAdd(&g_cursor[ei[EE + e]], 1);
        g_adj[pos] = e;
    }
}

// ---------------- tf32 tensor-core GEMM ----------------
// C[M,N] = act(X[M,K] @ W[K,N] + bias); 128x128 block tile, 8 warps.
// mode 0: bf16 -> g_xl_bf ; mode 1: bf16 -> g_xr_bf ; mode 2: f32 -> g_out ; mode 3: ELU f32 -> g_h

__device__ __forceinline__ uint32_t f2tf32(float v) {
    uint32_t o;
    asm("cvt.rna.tf32.f32 %0, %1;" : "=r"(o) : "f"(v));
    return o;
}

__device__ __forceinline__ void mma_tf32(float c[4], uint32_t a0, uint32_t a1,
                                         uint32_t a2, uint32_t a3, uint32_t b0, uint32_t b1) {
    asm volatile(
        "mma.sync.aligned.m16n8k8.row.col.f32.tf32.tf32.f32 "
        "{%0,%1,%2,%3},{%4,%5,%6,%7},{%8,%9},{%0,%1,%2,%3};"
        : "+f"(c[0]), "+f"(c[1]), "+f"(c[2]), "+f"(c[3])
        : "r"(a0), "r"(a1), "r"(a2), "r"(a3), "r"(b0), "r"(b1));
}

__global__ __launch_bounds__(256) void gemm_tc_k(
    const float* __restrict__ Xp, int x_is_gout,
    const float* __restrict__ W, const float* __restrict__ bias,
    int M, int K, int N, int mode) {
    __shared__ uint32_t s_a[128][36];
    __shared__ uint32_t s_b[32][136];
    const float* X = x_is_gout ? g_out : Xp;

    int tid = threadIdx.x;
    int lane = tid & 31, warp = tid >> 5;
    int wm = warp & 3, wn = warp >> 2;
    int m0 = wm * 32, n0 = wn * 64;
    int mBase = blockIdx.y * 128, nBase = blockIdx.x * 128;

    float acc[2][8][4];
#pragma unroll
    for (int mt = 0; mt < 2; mt++)
#pragma unroll
        for (int nt = 0; nt < 8; nt++)
#pragma unroll
            for (int c = 0; c < 4; c++) acc[mt][nt][c] = 0.f;

    int aRowBase = tid >> 3, aK4 = tid & 7;       // A: 4 rows per thread (stride 32)
    int bK = tid >> 3, bN4 = (tid & 7) * 4;       // B: row bK, 4 float4s

    for (int kb = 0; kb < K; kb += 32) {
        // load A chunk [128 x 32] with tf32 convert
#pragma unroll
        for (int i = 0; i < 4; i++) {
            int m = aRowBase + i * 32;
            int gr = mBase + m;
            float4 av = make_float4(0.f, 0.f, 0.f, 0.f);
            if (gr < M) av = *(const float4*)&X[(size_t)gr * K + kb + aK4 * 4];
            s_a[m][aK4 * 4 + 0] = f2tf32(av.x);
            s_a[m][aK4 * 4 + 1] = f2tf32(av.y);
            s_a[m][aK4 * 4 + 2] = f2tf32(av.z);
            s_a[m][aK4 * 4 + 3] = f2tf32(av.w);
        }
        // load B chunk [32 x 128]
#pragma unroll
        for (int i = 0; i < 4; i++) {
            int c4 = bN4 + i;
            float4 bv = *(const float4*)&W[(size_t)(kb + bK) * N + nBase + c4 * 4];
            s_b[bK][c4 * 4 + 0] = f2tf32(bv.x);
            s_b[bK][c4 * 4 + 1] = f2tf32(bv.y);
            s_b[bK][c4 * 4 + 2] = f2tf32(bv.z);
            s_b[bK][c4 * 4 + 3] = f2tf32(bv.w);
        }
        __syncthreads();

#pragma unroll
        for (int kk = 0; kk < 4; kk++) {
            uint32_t a[2][4];
#pragma unroll
            for (int mt = 0; mt < 2; mt++) {
                int r = m0 + mt * 16 + (lane >> 2);
                int c = kk * 8 + (lane & 3);
                a[mt][0] = s_a[r][c];
                a[mt][1] = s_a[r + 8][c];
                a[mt][2] = s_a[r][c + 4];
                a[mt][3] = s_a[r + 8][c + 4];
            }
#pragma unroll
            for (int nt = 0; nt < 8; nt++) {
                uint32_t b0 = s_b[kk * 8 + (lane & 3)][n0 + nt * 8 + (lane >> 2)];
                uint32_t b1 = s_b[kk * 8 + (lane & 3) + 4][n0 + nt * 8 + (lane >> 2)];
                mma_tf32(acc[0][nt], a[0][0], a[0][1], a[0][2], a[0][3], b0, b1);
                mma_tf32(acc[1][nt], a[1][0], a[1][1], a[1][2], a[1][3], b0, b1);
            }
        }
        __syncthreads();
    }

    // epilogue
#pragma unroll
    for (int mt = 0; mt < 2; mt++) {
#pragma unroll
        for (int nt = 0; nt < 8; nt++) {
            int r0 = mBase + m0 + mt * 16 + (lane >> 2);
            int cb = nBase + n0 + nt * 8 + (lane & 3) * 2;
            float bb0 = bias[cb], bb1 = bias[cb + 1];
            float v0 = acc[mt][nt][0] + bb0;
            float v1 = acc[mt][nt][1] + bb1;
            float v2 = acc[mt][nt][2] + bb0;
            float v3 = acc[mt][nt][3] + bb1;
            if (mode == 3) {
                v0 = v0 > 0.f ? v0 : (__expf(v0) - 1.f);
                v1 = v1 > 0.f ? v1 : (__expf(v1) - 1.f);
                v2 = v2 > 0.f ? v2 : (__expf(v2) - 1.f);
                v3 = v3 > 0.f ? v3 : (__expf(v3) - 1.f);
            }
            if (mode <= 1) {
                __nv_bfloat16* D = (mode == 0) ? g_xl_bf : g_xr_bf;
                if (r0 < M)
                    *(__nv_bfloat162*)&D[(size_t)r0 * N + cb] =
                        __floats2bfloat162_rn(v0, v1);
                if (r0 + 8 < M)
                    *(__nv_bfloat162*)&D[(size_t)(r0 + 8) * N + cb] =
                        __floats2bfloat162_rn(v2, v3);
            } else {
                float* D = (mode == 2) ? g_out : g_h;
                if (r0 < M) *(float2*)&D[(size_t)r0 * N + cb] = make_float2(v0, v1);
                if (r0 + 8 < M) *(float2*)&D[(size_t)(r0 + 8) * N + cb] = make_float2(v2, v3);
            }
        }
    }
}

// ---------------- per-edge GATv2 logits (bf16 gathers) ----------------
__global__ void edge_logits_k(const int* __restrict__ ei, const float* __restrict__ att) {
    __shared__ float s_att[1024];
    int tid = threadIdx.x;
#pragma unroll
    for (int i = 0; i < 4; i++) s_att[tid + i * 256] = att[tid + i * 256];
    __syncthreads();

    int e = blockIdx.x * 8 + (tid >> 5);
    int lane = tid & 31;
    if (e >= EE) return;
    size_t src = (size_t)ei[e];
    size_t dst = (size_t)ei[EE + e];
    const uint4* A = (const uint4*)&g_xl_bf[src * HCD];
    const uint4* B = (const uint4*)&g_xr_bf[dst * HCD];

#pragma unroll
    for (int it = 0; it < 4; it++) {
        int j = it * 32 + lane;  // covers bf16 elems j*8..j*8+7
        uint4 av = A[j], bv = B[j];
        const __nv_bfloat162* ap = (const __nv_bfloat162*)&av;
        const __nv_bfloat162* bp = (const __nv_bfloat162*)&bv;
        float v = 0.f;
#pragma unroll
        for (int q = 0; q < 4; q++) {
            float2 fa = __bfloat1622float2(ap[q]);
            float2 fb = __bfloat1622float2(bp[q]);
            float sx = fa.x + fb.x, sy = fa.y + fb.y;
            sx = sx > 0.f ? sx : NEG_SLOPE * sx;
            sy = sy > 0.f ? sy : NEG_SLOPE * sy;
            v += sx * s_att[j * 8 + q * 2] + sy * s_att[j * 8 + q * 2 + 1];
        }
        // reduce within 16-lane segment (one head per half-warp)
#pragma unroll
        for (int off = 8; off > 0; off >>= 1)
            v += __shfl_down_sync(0xffffffffu, v, off, 16);
        if ((lane & 15) == 0) {
            int h = it * 2 + (lane >> 4);
            g_ebuf[(size_t)e * 8 + h] = v;
        }
    }
}

// ---------------- per-node segment softmax + weighted aggregate ----------------
#define CHK 128
__global__ void node_aggregate_k(const int* __restrict__ ei) {
    int i = blockIdx.x;
    int beg = g_rowptr[i], end = g_rowptr[i + 1];
    int tid = threadIdx.x, lane = tid & 31, wid = tid >> 5;

    __shared__ float s_m[8], s_inv[8];
    __shared__ int s_src[CHK];
    __shared__ float s_alpha[CHK][9];

    float m = -3.4e38f;
    for (int k = beg + lane; k < end; k += 32)
        m = fmaxf(m, g_ebuf[(size_t)g_adj[k] * 8 + wid]);
#pragma unroll
    for (int off = 16; off > 0; off >>= 1) m = fmaxf(m, __shfl_xor_sync(0xffffffffu, m, off));
    float ssum = 0.f;
    for (int k = beg + lane; k < end; k += 32)
        ssum += __expf(g_ebuf[(size_t)g_adj[k] * 8 + wid] - m);
#pragma unroll
    for (int off = 16; off > 0; off >>= 1) ssum += __shfl_xor_sync(0xffffffffu, ssum, off);
    if (lane == 0) {
        s_m[wid] = m;
        s_inv[wid] = ssum > 0.f ? 1.f / ssum : 0.f;
    }
    __syncthreads();

    float acc0 = 0.f, acc1 = 0.f, acc2 = 0.f, acc3 = 0.f;
    int h = tid >> 5;  // thread covers channels tid*4..tid*4+3 ; head = tid/32

    for (int cb = beg; cb < end; cb += CHK) {
        int cnt = min(CHK, end - cb);
        if (tid < cnt) {
            int eid = g_adj[cb + tid];
            s_src[tid] = ei[eid];
#pragma unroll
            for (int hh = 0; hh < 8; hh++)
                s_alpha[tid][hh] = __expf(g_ebuf[(size_t)eid * 8 + hh] - s_m[hh]) * s_inv[hh];
        }
        __syncthreads();
        for (int k = 0; k < cnt; k++) {
            const uint2* xr = (const uint2*)&g_xl_bf[(size_t)s_src[k] * HCD];
            float a = s_alpha[k][h];
            uint2 raw = xr[tid];
            float2 p0 = __bfloat1622float2(*(const __nv_bfloat162*)&raw.x);
            float2 p1 = __bfloat1622float2(*(const __nv_bfloat162*)&raw.y);
            acc0 += a * p0.x;
            acc1 += a * p0.y;
            acc2 += a * p1.x;
            acc3 += a * p1.y;
        }
        __syncthreads();
    }

    float4* o = (float4*)&g_out[(size_t)i * HCD];
    float4 r = o[tid];
    o[tid] = make_float4(r.x + acc0, r.y + acc1, r.z + acc2, r.w + acc3);
}

// ---------------- deterministic mean pool (batch is sorted) ----------------
__global__ void pool_k(const int* __restrict__ batch) {
    int g = blockIdx.x;
    __shared__ int sb, se;
    __shared__ float red[256];
    if (threadIdx.x == 0) {
        int lo = 0, hi = NN;
        while (lo < hi) { int mid = (lo + hi) >> 1; if (batch[mid] < g) lo = mid + 1; else hi = mid; }
        sb = lo;
        lo = 0; hi = NN;
        while (lo < hi) { int mid = (lo + hi) >> 1; if (batch[mid] <= g) lo = mid + 1; else hi = mid; }
        se = lo;
    }
    __syncthreads();
    int beg = sb, end = se;
    int ch = threadIdx.x & 127, half = threadIdx.x >> 7;
    float acc = 0.f;
    for (int n = beg + half; n < end; n += 2) acc += g_h[(size_t)n * CC + ch];
    red[threadIdx.x] = acc;
    __syncthreads();
    if (half == 0) {
        float v = red[ch] + red[128 + ch];
        float c = (end > beg) ? (float)(end - beg) : 1.f;
        g_pooled[g * CC + ch] = v / c;
    }
}

// ---------------- MLP head: 128->16->32->5 ----------------
__global__ void head_k(const float* __restrict__ W1, const float* __restrict__ b1,
                       const float* __restrict__ W2, const float* __restrict__ b2,
                       const float* __restrict__ W3, const float* __restrict__ b3,
                       float* __restrict__ out) {
    __shared__ float sp[GG][CC];
    __shared__ float h1[GG][16];
    __shared__ float h2[GG][32];
    int tid = threadIdx.x;
    for (int idx = tid; idx < GG * CC; idx += 256) sp[idx >> 7][idx & 127] = g_pooled[idx];
    __syncthreads();
    for (int idx = tid; idx < GG * 16; idx += 256) {
        int g = idx / 16, o = idx % 16;
        float s = b1[o];
        for (int k = 0; k < CC; k++) s += sp[g][k] * W1[k * 16 + o];
        h1[g][o] = s > 0.f ? s : 0.f;
    }
    __syncthreads();
    for (int idx = tid; idx < GG * 32; idx += 256) {
        int g = idx / 32, o = idx % 32;
        float s = b2[o];
        for (int k = 0; k < 16; k++) s += h1[g][k] * W2[k * 32 + o];
        h2[g][o] = s > 0.f ? s : 0.f;
    }
    __syncthreads();
    for (int idx = tid; idx < GG * 5; idx += 256) {
        int g = idx / 5, o = idx % 5;
        float s = b3[o];
        for (int k = 0; k < 32; k++) s += h2[g][k] * W3[k * 5 + o];
        out[idx] = s;
    }
}

// ---------------- launch ----------------
extern "C" void kernel_launch(void* const* d_in, const int* in_sizes, int n_in,
                              void* d_out, int out_size) {
    const float* x = (const float*)d_in[0];
    const int* ei = (const int*)d_in[1];
    const int* batch = (const int*)d_in[2];
    const float* Wl = (const float*)d_in[3];
    const float* bl = (const float*)d_in[4];
    const float* Wr = (const float*)d_in[5];
    const float* br = (const float*)d_in[6];
    const float* att = (const float*)d_in[7];
    const float* Wres = (const float*)d_in[8];
    const float* bias_attn = (const float*)d_in[9];
    const float* W_lin = (const float*)d_in[10];
    const float* b_lin = (const float*)d_in[11];
    const float* W1 = (const float*)d_in[12];
    const float* b1 = (const float*)d_in[13];
    const float* W2 = (const float*)d_in[14];
    const float* b2 = (const float*)d_in[15];
    const float* W3 = (const float*)d_in[16];
    const float* b3 = (const float*)d_in[17];
    float* out = (float*)d_out;

    // CSR build
    init_k<<<(NN + 255) / 256, 256>>>();
    deg_k<<<(EE + 255) / 256, 256>>>(ei);
    scan_k<<<1, 1024>>>();
    adj_k<<<(EE + 255) / 256, 256>>>(ei);

    // dense transforms (tf32 tensor cores)
    dim3 blk(256);
    dim3 g1(HCD / 128, (NN + 127) / 128);
    gemm_tc_k<<<g1, blk>>>(x, 0, Wl, bl, NN, IND, HCD, 0);            // xl -> bf16
    gemm_tc_k<<<g1, blk>>>(x, 0, Wr, br, NN, IND, HCD, 1);            // xr -> bf16
    gemm_tc_k<<<g1, blk>>>(x, 0, Wres, bias_attn, NN, IND, HCD, 2);   // residual -> f32

    // GATv2 attention
    edge_logits_k<<<(EE + 7) / 8, 256>>>(ei, att);
    node_aggregate_k<<<NN, 256>>>(ei);

    // Linear + ELU (tf32 tensor cores)
    dim3 g2(CC / 128, (NN + 127) / 128);
    gemm_tc_k<<<g2, blk>>>(nullptr, 1, W_lin, b_lin, NN, HCD, CC, 3);

    // pool + head
    pool_k<<<GG, 256>>>(batch);
    head_k<<<1, 256>>>(W1, b1, W2, b2, W3, b3, out);
}

// round 5
// speedup vs baseline: 1.7019x; 1.1501x over previous
#include <cuda_runtime.h>
#include <cuda_bf16.h>
#include <math.h>
#include <stdint.h>

#define NN 20000
#define EE 320000
#define IND 128
#define HH 8
#define CC 128
#define HCD 1024
#define GG 64
#define NEG_SLOPE 0.2f

// ---------------- scratch (static device globals; no allocation) ----------------
__device__ __nv_bfloat16 g_xl_bf[(size_t)NN * HCD];   // x@Wl+bl (41 MB)
__device__ __nv_bfloat16 g_xr_bf[(size_t)NN * HCD];   // x@Wr+br (41 MB)
__device__ __nv_bfloat16 g_res_bf[(size_t)NN * HCD];  // residual -> attn output (41 MB)
__device__ float g_h[(size_t)NN * CC];                // ELU(Linear) (10 MB)
__device__ int   g_deg[NN];
__device__ int   g_rowptr[NN + 1];
__device__ int   g_cursor[NN];
__device__ int   g_adj[EE];
__device__ float g_pooled[GG * CC];

// ---------------- CSR build ----------------
__global__ void init_k() {
    int idx = blockIdx.x * 256 + threadIdx.x;
    if (idx < NN) g_deg[idx] = 0;
}

__global__ void deg_k(const int* __restrict__ ei) {
    int e = blockIdx.x * 256 + threadIdx.x;
    if (e < EE) atomicAdd(&g_deg[ei[EE + e]], 1);
}

// 1024 threads, 20 elems/thread serial + hierarchical block scan. One pass.
__global__ void scan_k() {
    __shared__ int warp_sums[32];
    int tid = threadIdx.x;
    int start = tid * 20;
    int v[20];
    int tot = 0;
#pragma unroll
    for (int j = 0; j < 20; j++) {
        int idx = start + j;
        int d = (idx < NN) ? g_deg[idx] : 0;
        v[j] = tot;       // exclusive prefix within thread
        tot += d;
    }
    // warp inclusive scan of tot
    int lane = tid & 31, wid = tid >> 5;
    int x = tot;
#pragma unroll
    for (int off = 1; off < 32; off <<= 1) {
        int t = __shfl_up_sync(0xffffffffu, x, off);
        if (lane >= off) x += t;
    }
    if (lane == 31) warp_sums[wid] = x;
    __syncthreads();
    if (wid == 0) {
        int w = (lane < 32) ? warp_sums[lane] : 0;
#pragma unroll
        for (int off = 1; off < 32; off <<= 1) {
            int t = __shfl_up_sync(0xffffffffu, w, off);
            if (lane >= off) w += t;
        }
        warp_sums[lane] = w;
    }
    __syncthreads();
    int base = x - tot + (wid > 0 ? warp_sums[wid - 1] : 0);  // exclusive offset for this thread
#pragma unroll
    for (int j = 0; j < 20; j++) {
        int idx = start + j;
        if (idx <= NN) {
            int ex = base + v[j];
            g_rowptr[idx] = ex;
            if (idx < NN) g_cursor[idx] = ex;
        }
    }
}

__global__ void adj_k(const int* __restrict__ ei) {
    int e = blockIdx.x * 256 + threadIdx.x;
    if (e < EE) {
        int pos = atomicAdd(&g_cursor[ei[EE + e]], 1);
        g_adj[pos] = e;
    }
}

// ---------------- tf32 tensor-core GEMM ----------------
// mode 0: bf16 -> g_xl_bf ; 1: bf16 -> g_xr_bf ; 2: bf16 -> g_res_bf ; 3: ELU f32 -> g_h
__device__ __forceinline__ uint32_t f2tf32(float v) {
    uint32_t o;
    asm("cvt.rna.tf32.f32 %0, %1;" : "=r"(o) : "f"(v));
    return o;
}

__device__ __forceinline__ void mma_tf32(float c[4], uint32_t a0, uint32_t a1,
                                         uint32_t a2, uint32_t a3, uint32_t b0, uint32_t b1) {
    asm volatile(
        "mma.sync.aligned.m16n8k8.row.col.f32.tf32.tf32.f32 "
        "{%0,%1,%2,%3},{%4,%5,%6,%7},{%8,%9},{%0,%1,%2,%3};"
        : "+f"(c[0]), "+f"(c[1]), "+f"(c[2]), "+f"(c[3])
        : "r"(a0), "r"(a1), "r"(a2), "r"(a3), "r"(b0), "r"(b1));
}

__global__ __launch_bounds__(256) void gemm_tc_k(
    const float* __restrict__ Xf, int a_bf16,
    const float* __restrict__ W, const float* __restrict__ bias,
    int M, int K, int N, int mode) {
    __shared__ uint32_t s_a[128][36];
    __shared__ uint32_t s_b[32][136];

    int tid = threadIdx.x;
    int lane = tid & 31, warp = tid >> 5;
    int wm = warp & 3, wn = warp >> 2;
    int m0 = wm * 32, n0 = wn * 64;
    int mBase = blockIdx.y * 128, nBase = blockIdx.x * 128;

    float acc[2][8][4];
#pragma unroll
    for (int mt = 0; mt < 2; mt++)
#pragma unroll
        for (int nt = 0; nt < 8; nt++)
#pragma unroll
            for (int c = 0; c < 4; c++) acc[mt][nt][c] = 0.f;

    int bK = tid >> 3, bN4 = (tid & 7) * 4;

    for (int kb = 0; kb < K; kb += 32) {
        // ---- load A chunk [128 x 32] -> tf32 ----
        if (!a_bf16) {
            int aRowBase = tid >> 3, aK4 = tid & 7;
#pragma unroll
            for (int i = 0; i < 4; i++) {
                int m = aRowBase + i * 32;
                int gr = mBase + m;
                float4 av = make_float4(0.f, 0.f, 0.f, 0.f);
                if (gr < M) av = *(const float4*)&Xf[(size_t)gr * K + kb + aK4 * 4];
                s_a[m][aK4 * 4 + 0] = f2tf32(av.x);
                s_a[m][aK4 * 4 + 1] = f2tf32(av.y);
                s_a[m][aK4 * 4 + 2] = f2tf32(av.z);
                s_a[m][aK4 * 4 + 3] = f2tf32(av.w);
            }
        } else {
            int aRowBase = tid >> 2, aQ = tid & 3;  // 8 bf16 per thread
#pragma unroll
            for (int i = 0; i < 2; i++) {
                int m = aRowBase + i * 64;
                int gr = mBase + m;
                uint4 raw = make_uint4(0u, 0u, 0u, 0u);
                if (gr < M) raw = *(const uint4*)&g_res_bf[(size_t)gr * K + kb + aQ * 8];
                const __nv_bfloat162* p = (const __nv_bfloat162*)&raw;
#pragma unroll
                for (int q = 0; q < 4; q++) {
                    float2 f = __bfloat1622float2(p[q]);
                    s_a[m][aQ * 8 + q * 2 + 0] = f2tf32(f.x);
                    s_a[m][aQ * 8 + q * 2 + 1] = f2tf32(f.y);
                }
            }
        }
        // ---- load B chunk [32 x 128] ----
#pragma unroll
        for (int i = 0; i < 4; i++) {
            int c4 = bN4 + i;
            float4 bv = *(const float4*)&W[(size_t)(kb + bK) * N + nBase + c4 * 4];
            s_b[bK][c4 * 4 + 0] = f2tf32(bv.x);
            s_b[bK][c4 * 4 + 1] = f2tf32(bv.y);
            s_b[bK][c4 * 4 + 2] = f2tf32(bv.z);
            s_b[bK][c4 * 4 + 3] = f2tf32(bv.w);
        }
        __syncthreads();

#pragma unroll
        for (int kk = 0; kk < 4; kk++) {
            uint32_t a[2][4];
#pragma unroll
            for (int mt = 0; mt < 2; mt++) {
                int r = m0 + mt * 16 + (lane >> 2);
                int c = kk * 8 + (lane & 3);
                a[mt][0] = s_a[r][c];
                a[mt][1] = s_a[r + 8][c];
                a[mt][2] = s_a[r][c + 4];
                a[mt][3] = s_a[r + 8][c + 4];
            }
#pragma unroll
            for (int nt = 0; nt < 8; nt++) {
                uint32_t b0 = s_b[kk * 8 + (lane & 3)][n0 + nt * 8 + (lane >> 2)];
                uint32_t b1 = s_b[kk * 8 + (lane & 3) + 4][n0 + nt * 8 + (lane >> 2)];
                mma_tf32(acc[0][nt], a[0][0], a[0][1], a[0][2], a[0][3], b0, b1);
                mma_tf32(acc[1][nt], a[1][0], a[1][1], a[1][2], a[1][3], b0, b1);
            }
        }
        __syncthreads();
    }

#pragma unroll
    for (int mt = 0; mt < 2; mt++) {
#pragma unroll
        for (int nt = 0; nt < 8; nt++) {
            int r0 = mBase + m0 + mt * 16 + (lane >> 2);
            int cb = nBase + n0 + nt * 8 + (lane & 3) * 2;
            float bb0 = bias[cb], bb1 = bias[cb + 1];
            float v0 = acc[mt][nt][0] + bb0;
            float v1 = acc[mt][nt][1] + bb1;
            float v2 = acc[mt][nt][2] + bb0;
            float v3 = acc[mt][nt][3] + bb1;
            if (mode == 3) {
                v0 = v0 > 0.f ? v0 : (__expf(v0) - 1.f);
                v1 = v1 > 0.f ? v1 : (__expf(v1) - 1.f);
                v2 = v2 > 0.f ? v2 : (__expf(v2) - 1.f);
                v3 = v3 > 0.f ? v3 : (__expf(v3) - 1.f);
                if (r0 < M) *(float2*)&g_h[(size_t)r0 * N + cb] = make_float2(v0, v1);
                if (r0 + 8 < M) *(float2*)&g_h[(size_t)(r0 + 8) * N + cb] = make_float2(v2, v3);
            } else {
                __nv_bfloat16* D = (mode == 0) ? g_xl_bf : (mode == 1 ? g_xr_bf : g_res_bf);
                if (r0 < M)
                    *(__nv_bfloat162*)&D[(size_t)r0 * N + cb] = __floats2bfloat162_rn(v0, v1);
                if (r0 + 8 < M)
                    *(__nv_bfloat162*)&D[(size_t)(r0 + 8) * N + cb] = __floats2bfloat162_rn(v2, v3);
            }
        }
    }
}

// ---------------- fused per-node GATv2: logits + online softmax + aggregate ----------------
#define CHKF 256
__global__ __launch_bounds__(256) void node_attn_k(const int* __restrict__ ei,
                                                   const float* __restrict__ att) {
    int i = blockIdx.x;
    int tid = threadIdx.x, lane = tid & 31, wid = tid >> 5;
    int beg = g_rowptr[i], end = g_rowptr[i + 1];

    __shared__ float s_att[HCD];              // 4 KB
    __shared__ float s_xr[HCD];               // 4 KB
    __shared__ float s_logit[CHKF][9];        // 9 KB (logits, then exp-weights)
    __shared__ int   s_src[CHKF];             // 1 KB
    __shared__ float s_scale[HH];
    __shared__ float s_inv[HH];

    // load att + xr row
#pragma unroll
    for (int q = 0; q < 4; q++) s_att[tid + q * 256] = att[tid + q * 256];
    if (tid < 128) {
        uint4 raw = ((const uint4*)&g_xr_bf[(size_t)i * HCD])[tid];
        const __nv_bfloat162* p = (const __nv_bfloat162*)&raw;
#pragma unroll
        for (int q = 0; q < 4; q++) {
            float2 f = __bfloat1622float2(p[q]);
            s_xr[tid * 8 + q * 2 + 0] = f.x;
            s_xr[tid * 8 + q * 2 + 1] = f.y;
        }
    }
    __syncthreads();

    float run_m = -3.4e38f, run_s = 0.f;                  // per-head (warp wid owns head wid)
    float acc0 = 0.f, acc1 = 0.f, acc2 = 0.f, acc3 = 0.f; // channels tid*4..+3, head h
    int h = tid >> 5;

    for (int cb = beg; cb < end; cb += CHKF) {
        int cnt = min(CHKF, end - cb);

        // ---- phase 1: logits for this chunk (warp per edge, strided) ----
        for (int k = wid; k < cnt; k += 8) {
            int eid = g_adj[cb + k];
            int src = ei[eid];
            if (lane == 0) s_src[k] = src;
            const uint4* A = (const uint4*)&g_xl_bf[(size_t)src * HCD];
#pragma unroll
            for (int it = 0; it < 4; it++) {
                int j = it * 32 + lane;
                uint4 av = A[j];
                const __nv_bfloat162* ap = (const __nv_bfloat162*)&av;
                float v = 0.f;
#pragma unroll
                for (int q = 0; q < 4; q++) {
                    float2 fa = __bfloat1622float2(ap[q]);
                    float sx = fa.x + s_xr[j * 8 + q * 2];
                    float sy = fa.y + s_xr[j * 8 + q * 2 + 1];
                    sx = sx > 0.f ? sx : NEG_SLOPE * sx;
                    sy = sy > 0.f ? sy : NEG_SLOPE * sy;
                    v += sx * s_att[j * 8 + q * 2] + sy * s_att[j * 8 + q * 2 + 1];
                }
#pragma unroll
                for (int off = 8; off > 0; off >>= 1)
                    v += __shfl_down_sync(0xffffffffu, v, off, 16);
                if ((lane & 15) == 0) s_logit[k][it * 2 + (lane >> 4)] = v;
            }
        }
        __syncthreads();

        // ---- phase 2: per-head streaming stats merge (warp wid = head wid) ----
        {
            float cm = -3.4e38f;
            for (int k = lane; k < cnt; k += 32) cm = fmaxf(cm, s_logit[k][wid]);
#pragma unroll
            for (int off = 16; off > 0; off >>= 1)
                cm = fmaxf(cm, __shfl_xor_sync(0xffffffffu, cm, off));
            float nm = fmaxf(run_m, cm);
            float csum = 0.f;
            for (int k = lane; k < cnt; k += 32) {
                float w = __expf(s_logit[k][wid] - nm);
                s_logit[k][wid] = w;
                csum += w;
            }
#pragma unroll
            for (int off = 16; off > 0; off >>= 1)
                csum += __shfl_xor_sync(0xffffffffu, csum, off);
            float scale = __expf(run_m - nm);
            run_s = run_s * scale + csum;
            run_m = nm;
            if (lane == 0) s_scale[wid] = scale;
        }
        __syncthreads();

        // ---- phase 3: weighted aggregate ----
        float sc = s_scale[h];
        acc0 *= sc; acc1 *= sc; acc2 *= sc; acc3 *= sc;
        for (int k = 0; k < cnt; k++) {
            float a = s_logit[k][h];
            uint2 raw = ((const uint2*)&g_xl_bf[(size_t)s_src[k] * HCD])[tid];
            float2 p0 = __bfloat1622float2(*(const __nv_bfloat162*)&raw.x);
            float2 p1 = __bfloat1622float2(*(const __nv_bfloat162*)&raw.y);
            acc0 += a * p0.x;
            acc1 += a * p0.y;
            acc2 += a * p1.x;
            acc3 += a * p1.y;
        }
        __syncthreads();
    }

    if (lane == 0) s_inv[wid] = (run_s > 0.f) ? 1.f / run_s : 0.f;
    __syncthreads();
    float inv = s_inv[h];

    // residual add + store bf16 (RMW on g_res_bf)
    uint2* orow = (uint2*)&g_res_bf[(size_t)i * HCD];
    uint2 rraw = orow[tid];
    float2 r0 = __bfloat1622float2(*(const __nv_bfloat162*)&rraw.x);
    float2 r1 = __bfloat1622float2(*(const __nv_bfloat162*)&rraw.y);
    __nv_bfloat162 o0 = __floats2bfloat162_rn(acc0 * inv + r0.x, acc1 * inv + r0.y);
    __nv_bfloat162 o1 = __floats2bfloat162_rn(acc2 * inv + r1.x, acc3 * inv + r1.y);
    uint2 w;
    w.x = *(const uint32_t*)&o0;
    w.y = *(const uint32_t*)&o1;
    orow[tid] = w;
}

// ---------------- deterministic mean pool (batch sorted) ----------------
__global__ void pool_k(const int* __restrict__ batch) {
    int g = blockIdx.x;
    __shared__ int sb, se;
    __shared__ float red[256];
    if (threadIdx.x == 0) {
        int lo = 0, hi = NN;
        while (lo < hi) { int mid = (lo + hi) >> 1; if (batch[mid] < g) lo = mid + 1; else hi = mid; }
        sb = lo;
        lo = 0; hi = NN;
        while (lo < hi) { int mid = (lo + hi) >> 1; if (batch[mid] <= g) lo = mid + 1; else hi = mid; }
        se = lo;
    }
    __syncthreads();
    int beg = sb, end = se;
    int ch = threadIdx.x & 127, half = threadIdx.x >> 7;
    float acc = 0.f;
    for (int n = beg + half; n < end; n += 2) acc += g_h[(size_t)n * CC + ch];
    red[threadIdx.x] = acc;
    __syncthreads();
    if (half == 0) {
        float v = red[ch] + red[128 + ch];
        float c = (end > beg) ? (float)(end - beg) : 1.f;
        g_pooled[g * CC + ch] = v / c;
    }
}

// ---------------- MLP head ----------------
__global__ void head_k(const float* __restrict__ W1, const float* __restrict__ b1,
                       const float* __restrict__ W2, const float* __restrict__ b2,
                       const float* __restrict__ W3, const float* __restrict__ b3,
                       float* __restrict__ out) {
    __shared__ float sp[GG][CC];
    __shared__ float h1[GG][16];
    __shared__ float h2[GG][32];
    int tid = threadIdx.x;
    for (int idx = tid; idx < GG * CC; idx += 256) sp[idx >> 7][idx & 127] = g_pooled[idx];
    __syncthreads();
    for (int idx = tid; idx < GG * 16; idx += 256) {
        int g = idx / 16, o = idx % 16;
        float s = b1[o];
        for (int k = 0; k < CC; k++) s += sp[g][k] * W1[k * 16 + o];
        h1[g][o] = s > 0.f ? s : 0.f;
    }
    __syncthreads();
    for (int idx = tid; idx < GG * 32; idx += 256) {
        int g = idx / 32, o = idx % 32;
        float s = b2[o];
        for (int k = 0; k < 16; k++) s += h1[g][k] * W2[k * 32 + o];
        h2[g][o] = s > 0.f ? s : 0.f;
    }
    __syncthreads();
    for (int idx = tid; idx < GG * 5; idx += 256) {
        int g = idx / 5, o = idx % 5;
        float s = b3[o];
        for (int k = 0; k < 32; k++) s += h2[g][k] * W3[k * 5 + o];
        out[idx] = s;
    }
}

// ---------------- launch ----------------
extern "C" void kernel_launch(void* const* d_in, const int* in_sizes, int n_in,
                              void* d_out, int out_size) {
    const float* x = (const float*)d_in[0];
    const int* ei = (const int*)d_in[1];
    const int* batch = (const int*)d_in[2];
    const float* Wl = (const float*)d_in[3];
    const float* bl = (const float*)d_in[4];
    const float* Wr = (const float*)d_in[5];
    const float* br = (const float*)d_in[6];
    const float* att = (const float*)d_in[7];
    const float* Wres = (const float*)d_in[8];
    const float* bias_attn = (const float*)d_in[9];
    const float* W_lin = (const float*)d_in[10];
    const float* b_lin = (const float*)d_in[11];
    const float* W1 = (const float*)d_in[12];
    const float* b1 = (const float*)d_in[13];
    const float* W2 = (const float*)d_in[14];
    const float* b2 = (const float*)d_in[15];
    const float* W3 = (const float*)d_in[16];
    const float* b3 = (const float*)d_in[17];
    float* out = (float*)d_out;

    // CSR build
    init_k<<<(NN + 255) / 256, 256>>>();
    deg_k<<<(EE + 255) / 256, 256>>>(ei);
    scan_k<<<1, 1024>>>();
    adj_k<<<(EE + 255) / 256, 256>>>(ei);

    // dense transforms (tf32 tensor cores)
    dim3 blk(256);
    dim3 g1(HCD / 128, (NN + 127) / 128);
    gemm_tc_k<<<g1, blk>>>(x, 0, Wl, bl, NN, IND, HCD, 0);            // xl -> bf16
    gemm_tc_k<<<g1, blk>>>(x, 0, Wr, br, NN, IND, HCD, 1);            // xr -> bf16
    gemm_tc_k<<<g1, blk>>>(x, 0, Wres, bias_attn, NN, IND, HCD, 2);   // residual -> bf16

    // fused GATv2 attention (logits + softmax + aggregate + residual)
    node_attn_k<<<NN, 256>>>(ei, att);

    // Linear + ELU (bf16 A input)
    dim3 g2(CC / 128, (NN + 127) / 128);
    gemm_tc_k<<<g2, blk>>>(nullptr, 1, W_lin, b_lin, NN, HCD, CC, 3);

    // pool + head
    pool_k<<<GG, 256>>>(batch);
    head_k<<<1, 256>>>(W1, b1, W2, b2, W3, b3, out);
}

// round 7
// speedup vs baseline: 1.9857x; 1.1667x over previous
#include <cuda_runtime.h>
#include <cuda_bf16.h>
#include <math.h>
#include <stdint.h>

#define NN 20000
#define EE 320000
#define IND 128
#define HH 8
#define CC 128
#define HCD 1024
#define GG 64
#define NEG_SLOPE 0.2f

// ---------------- scratch (static device globals; no allocation) ----------------
__device__ __nv_bfloat16 g_xl_bf[(size_t)NN * HCD];   // x@Wl+bl (41 MB)
__device__ __nv_bfloat16 g_xr_bf[(size_t)NN * HCD];   // x@Wr+br (41 MB)
__device__ float g_out[(size_t)NN * HCD];             // residual -> attn output (82 MB, fp32)
__device__ float g_h[(size_t)NN * CC];                // ELU(Linear) (10 MB)
__device__ int   g_deg[NN];
__device__ int   g_rowptr[NN + 1];
__device__ int   g_cursor[NN];
__device__ int   g_adj[EE];
__device__ float g_pooled[GG * CC];

// ---------------- CSR build ----------------
__global__ void init_k() {
    int idx = blockIdx.x * 256 + threadIdx.x;
    if (idx < NN) g_deg[idx] = 0;
}

__global__ void deg_k(const int* __restrict__ ei) {
    int e = blockIdx.x * 256 + threadIdx.x;
    if (e < EE) atomicAdd(&g_deg[ei[EE + e]], 1);
}

__global__ void scan_k() {
    __shared__ int warp_sums[32];
    int tid = threadIdx.x;
    int start = tid * 20;
    int v[20];
    int tot = 0;
#pragma unroll
    for (int j = 0; j < 20; j++) {
        int idx = start + j;
        int d = (idx < NN) ? g_deg[idx] : 0;
        v[j] = tot;
        tot += d;
    }
    int lane = tid & 31, wid = tid >> 5;
    int x = tot;
#pragma unroll
    for (int off = 1; off < 32; off <<= 1) {
        int t = __shfl_up_sync(0xffffffffu, x, off);
        if (lane >= off) x += t;
    }
    if (lane == 31) warp_sums[wid] = x;
    __syncthreads();
    if (wid == 0) {
        int w = warp_sums[lane];
#pragma unroll
        for (int off = 1; off < 32; off <<= 1) {
            int t = __shfl_up_sync(0xffffffffu, w, off);
            if (lane >= off) w += t;
        }
        warp_sums[lane] = w;
    }
    __syncthreads();
    int base = x - tot + (wid > 0 ? warp_sums[wid - 1] : 0);
#pragma unroll
    for (int j = 0; j < 20; j++) {
        int idx = start + j;
        if (idx <= NN) {
            int ex = base + v[j];
            g_rowptr[idx] = ex;
            if (idx < NN) g_cursor[idx] = ex;
        }
    }
}

__global__ void adj_k(const int* __restrict__ ei) {
    int e = blockIdx.x * 256 + threadIdx.x;
    if (e < EE) {
        int pos = atomicAdd(&g_cursor[ei[EE + e]], 1);
        g_adj[pos] = e;
    }
}

// ---------------- bf16 tensor-core GEMM (m16n8k16, fp32 accumulate) ----------------
// mode 0: bf16 -> g_xl_bf ; 1: bf16 -> g_xr_bf ; 2: f32 -> g_out ; 3: ELU f32 -> g_h
__device__ __forceinline__ void mma_bf16(float c[4], uint32_t a0, uint32_t a1,
                                         uint32_t a2, uint32_t a3, uint32_t b0, uint32_t b1) {
    asm volatile(
        "mma.sync.aligned.m16n8k16.row.col.f32.bf16.bf16.f32 "
        "{%0,%1,%2,%3},{%4,%5,%6,%7},{%8,%9},{%0,%1,%2,%3};"
        : "+f"(c[0]), "+f"(c[1]), "+f"(c[2]), "+f"(c[3])
        : "r"(a0), "r"(a1), "r"(a2), "r"(a3), "r"(b0), "r"(b1));
}

__device__ __forceinline__ uint32_t pack_bf16x2(float lo, float hi) {
    __nv_bfloat162 p = __floats2bfloat162_rn(lo, hi);
    return *(const uint32_t*)&p;
}

__global__ __launch_bounds__(256) void gemm_tc_k(
    const float* __restrict__ Xf, int x_is_gout,
    const float* __restrict__ W, const float* __restrict__ bias,
    int M, int K, int N, int mode) {
    // packed bf16x2 operands: s_a[m][k2] (K/2 pairs), s_b[k2][n]
    __shared__ uint32_t s_a[128][18];   // 16 k2 + pad2
    __shared__ uint32_t s_b[16][132];   // 128 n + pad4

    const float* X = x_is_gout ? g_out : Xf;
    int tid = threadIdx.x;
    int lane = tid & 31, warp = tid >> 5;
    int wm = warp & 3, wn = warp >> 2;
    int m0 = wm * 32, n0 = wn * 64;
    int mBase = blockIdx.y * 128, nBase = blockIdx.x * 128;

    float acc[2][8][4];
#pragma unroll
    for (int mt = 0; mt < 2; mt++)
#pragma unroll
        for (int nt = 0; nt < 8; nt++)
#pragma unroll
            for (int c = 0; c < 4; c++) acc[mt][nt][c] = 0.f;

    int aRowBase = tid >> 3, aK4 = tid & 7;   // A: float4 -> 2 packed pairs
    int bK2 = tid >> 4, bN4b = (tid & 15) * 2; // B: (k2, two float4-col groups)

    for (int kb = 0; kb < K; kb += 32) {
        // ---- A chunk [128 x 32] fp32 -> bf16x2 pairs ----
#pragma unroll
        for (int i = 0; i < 4; i++) {
            int m = aRowBase + i * 32;
            int gr = mBase + m;
            float4 av = make_float4(0.f, 0.f, 0.f, 0.f);
            if (gr < M) av = *(const float4*)&X[(size_t)gr * K + kb + aK4 * 4];
            s_a[m][aK4 * 2 + 0] = pack_bf16x2(av.x, av.y);
            s_a[m][aK4 * 2 + 1] = pack_bf16x2(av.z, av.w);
        }
        // ---- B chunk [32 x 128] -> pairs along K ----
#pragma unroll
        for (int i = 0; i < 2; i++) {
            int n4 = bN4b + i;
            const float4 b0v = *(const float4*)&W[(size_t)(kb + bK2 * 2) * N + nBase + n4 * 4];
            const float4 b1v = *(const float4*)&W[(size_t)(kb + bK2 * 2 + 1) * N + nBase + n4 * 4];
            s_b[bK2][n4 * 4 + 0] = pack_bf16x2(b0v.x, b1v.x);
            s_b[bK2][n4 * 4 + 1] = pack_bf16x2(b0v.y, b1v.y);
            s_b[bK2][n4 * 4 + 2] = pack_bf16x2(b0v.z, b1v.z);
            s_b[bK2][n4 * 4 + 3] = pack_bf16x2(b0v.w, b1v.w);
        }
        __syncthreads();

#pragma unroll
        for (int kk = 0; kk < 2; kk++) {  // two k16 steps per 32-chunk
            uint32_t a[2][4];
#pragma unroll
            for (int mt = 0; mt < 2; mt++) {
                int r = m0 + mt * 16 + (lane >> 2);
                int c = kk * 8 + (lane & 3);
                a[mt][0] = s_a[r][c];
                a[mt][1] = s_a[r + 8][c];
                a[mt][2] = s_a[r][c + 4];
                a[mt][3] = s_a[r + 8][c + 4];
            }
#pragma unroll
            for (int nt = 0; nt < 8; nt++) {
                int n = n0 + nt * 8 + (lane >> 2);
                uint32_t b0 = s_b[kk * 8 + (lane & 3)][n];
                uint32_t b1 = s_b[kk * 8 + (lane & 3) + 4][n];
                mma_bf16(acc[0][nt], a[0][0], a[0][1], a[0][2], a[0][3], b0, b1);
                mma_bf16(acc[1][nt], a[1][0], a[1][1], a[1][2], a[1][3], b0, b1);
            }
        }
        __syncthreads();
    }

#pragma unroll
    for (int mt = 0; mt < 2; mt++) {
#pragma unroll
        for (int nt = 0; nt < 8; nt++) {
            int r0 = mBase + m0 + mt * 16 + (lane >> 2);
            int cb = nBase + n0 + nt * 8 + (lane & 3) * 2;
            float bb0 = bias[cb], bb1 = bias[cb + 1];
            float v0 = acc[mt][nt][0] + bb0;
            float v1 = acc[mt][nt][1] + bb1;
            float v2 = acc[mt][nt][2] + bb0;
            float v3 = acc[mt][nt][3] + bb1;
            if (mode == 3) {
                v0 = v0 > 0.f ? v0 : (__expf(v0) - 1.f);
                v1 = v1 > 0.f ? v1 : (__expf(v1) - 1.f);
                v2 = v2 > 0.f ? v2 : (__expf(v2) - 1.f);
                v3 = v3 > 0.f ? v3 : (__expf(v3) - 1.f);
                if (r0 < M) *(float2*)&g_h[(size_t)r0 * N + cb] = make_float2(v0, v1);
                if (r0 + 8 < M) *(float2*)&g_h[(size_t)(r0 + 8) * N + cb] = make_float2(v2, v3);
            } else if (mode == 2) {
                if (r0 < M) *(float2*)&g_out[(size_t)r0 * N + cb] = make_float2(v0, v1);
                if (r0 + 8 < M) *(float2*)&g_out[(size_t)(r0 + 8) * N + cb] = make_float2(v2, v3);
            } else {
                __nv_bfloat16* D = (mode == 0) ? g_xl_bf : g_xr_bf;
                if (r0 < M)
                    *(__nv_bfloat162*)&D[(size_t)r0 * N + cb] = __floats2bfloat162_rn(v0, v1);
                if (r0 + 8 < M)
                    *(__nv_bfloat162*)&D[(size_t)(r0 + 8) * N + cb] = __floats2bfloat162_rn(v2, v3);
            }
        }
    }
}

// ---------------- fused per-node GATv2: logits + online softmax + aggregate ----------------
#define CHKF 256
__global__ __launch_bounds__(256) void node_attn_k(const int* __restrict__ ei,
                                                   const float* __restrict__ att) {
    int i = blockIdx.x;
    int tid = threadIdx.x, lane = tid & 31, wid = tid >> 5;
    int beg = g_rowptr[i], end = g_rowptr[i + 1];

    __shared__ float s_att[HCD];
    __shared__ float s_xr[HCD];
    __shared__ float s_logit[CHKF][9];
    __shared__ int   s_src[CHKF];
    __shared__ float s_scale[HH];
    __shared__ float s_inv[HH];

#pragma unroll
    for (int q = 0; q < 4; q++) s_att[tid + q * 256] = att[tid + q * 256];
    if (tid < 128) {
        uint4 raw = ((const uint4*)&g_xr_bf[(size_t)i * HCD])[tid];
        const __nv_bfloat162* p = (const __nv_bfloat162*)&raw;
#pragma unroll
        for (int q = 0; q < 4; q++) {
            float2 f = __bfloat1622float2(p[q]);
            s_xr[tid * 8 + q * 2 + 0] = f.x;
            s_xr[tid * 8 + q * 2 + 1] = f.y;
        }
    }
    __syncthreads();

    float run_m = -3.4e38f, run_s = 0.f;
    float acc0 = 0.f, acc1 = 0.f, acc2 = 0.f, acc3 = 0.f;
    int h = tid >> 5;

    for (int cb = beg; cb < end; cb += CHKF) {
        int cnt = min(CHKF, end - cb);

        // phase 1: logits (warp per edge)
        for (int k = wid; k < cnt; k += 8) {
            int eid = g_adj[cb + k];
            int src = ei[eid];
            if (lane == 0) s_src[k] = src;
            const uint4* A = (const uint4*)&g_xl_bf[(size_t)src * HCD];
#pragma unroll
            for (int it = 0; it < 4; it++) {
                int j = it * 32 + lane;
                uint4 av = A[j];
                const __nv_bfloat162* ap = (const __nv_bfloat162*)&av;
                float v = 0.f;
#pragma unroll
                for (int q = 0; q < 4; q++) {
                    float2 fa = __bfloat1622float2(ap[q]);
                    float sx = fa.x + s_xr[j * 8 + q * 2];
                    float sy = fa.y + s_xr[j * 8 + q * 2 + 1];
                    sx = sx > 0.f ? sx : NEG_SLOPE * sx;
                    sy = sy > 0.f ? sy : NEG_SLOPE * sy;
                    v += sx * s_att[j * 8 + q * 2] + sy * s_att[j * 8 + q * 2 + 1];
                }
#pragma unroll
                for (int off = 8; off > 0; off >>= 1)
                    v += __shfl_down_sync(0xffffffffu, v, off, 16);
                if ((lane & 15) == 0) s_logit[k][it * 2 + (lane >> 4)] = v;
            }
        }
        __syncthreads();

        // phase 2: per-head streaming stats (warp wid = head wid)
        {
            float cm = -3.4e38f;
            for (int k = lane; k < cnt; k += 32) cm = fmaxf(cm, s_logit[k][wid]);
#pragma unroll
            for (int off = 16; off > 0; off >>= 1)
                cm = fmaxf(cm, __shfl_xor_sync(0xffffffffu, cm, off));
            float nm = fmaxf(run_m, cm);
            float csum = 0.f;
            for (int k = lane; k < cnt; k += 32) {
                float w = __expf(s_logit[k][wid] - nm);
                s_logit[k][wid] = w;
                csum += w;
            }
#pragma unroll
            for (int off = 16; off > 0; off >>= 1)
                csum += __shfl_xor_sync(0xffffffffu, csum, off);
            float scale = __expf(run_m - nm);
            run_s = run_s * scale + csum;
            run_m = nm;
            if (lane == 0) s_scale[wid] = scale;
        }
        __syncthreads();

        // phase 3: weighted aggregate
        float sc = s_scale[h];
        acc0 *= sc; acc1 *= sc; acc2 *= sc; acc3 *= sc;
        for (int k = 0; k < cnt; k++) {
            float a = s_logit[k][h];
            uint2 raw = ((const uint2*)&g_xl_bf[(size_t)s_src[k] * HCD])[tid];
            float2 p0 = __bfloat1622float2(*(const __nv_bfloat162*)&raw.x);
            float2 p1 = __bfloat1622float2(*(const __nv_bfloat162*)&raw.y);
            acc0 += a * p0.x;
            acc1 += a * p0.y;
            acc2 += a * p1.x;
            acc3 += a * p1.y;
        }
        __syncthreads();
    }

    if (lane == 0) s_inv[wid] = (run_s > 0.f) ? 1.f / run_s : 0.f;
    __syncthreads();
    float inv = s_inv[h];

    // residual add, fp32 RMW
    float4* orow = (float4*)&g_out[(size_t)i * HCD];
    float4 r = orow[tid];
    orow[tid] = make_float4(acc0 * inv + r.x, acc1 * inv + r.y,
                            acc2 * inv + r.z, acc3 * inv + r.w);
}

// ---------------- deterministic mean pool (batch sorted) ----------------
__global__ void pool_k(const int* __restrict__ batch) {
    int g = blockIdx.x;
    __shared__ int sb, se;
    __shared__ float red[256];
    if (threadIdx.x == 0) {
        int lo = 0, hi = NN;
        while (lo < hi) { int mid = (lo + hi) >> 1; if (batch[mid] < g) lo = mid + 1; else hi = mid; }
        sb = lo;
        lo = 0; hi = NN;
        while (lo < hi) { int mid = (lo + hi) >> 1; if (batch[mid] <= g) lo = mid + 1; else hi = mid; }
        se = lo;
    }
    __syncthreads();
    int beg = sb, end = se;
    int ch = threadIdx.x & 127, half = threadIdx.x >> 7;
    float acc = 0.f;
    for (int n = beg + half; n < end; n += 2) acc += g_h[(size_t)n * CC + ch];
    red[threadIdx.x] = acc;
    __syncthreads();
    if (half == 0) {
        float v = red[ch] + red[128 + ch];
        float c = (end > beg) ? (float)(end - beg) : 1.f;
        g_pooled[g * CC + ch] = v / c;
    }
}

// ---------------- MLP head ----------------
__global__ void head_k(const float* __restrict__ W1, const float* __restrict__ b1,
                       const float* __restrict__ W2, const float* __restrict__ b2,
                       const float* __restrict__ W3, const float* __restrict__ b3,
                       float* __restrict__ out) {
    __shared__ float sp[GG][CC];
    __shared__ float h1[GG][16];
    __shared__ float h2[GG][32];
    int tid = threadIdx.x;
    for (int idx = tid; idx < GG * CC; idx += 256) sp[idx >> 7][idx & 127] = g_pooled[idx];
    __syncthreads();
    for (int idx = tid; idx < GG * 16; idx += 256) {
        int g = idx / 16, o = idx % 16;
        float s = b1[o];
        for (int k = 0; k < CC; k++) s += sp[g][k] * W1[k * 16 + o];
        h1[g][o] = s > 0.f ? s : 0.f;
    }
    __syncthreads();
    for (int idx = tid; idx < GG * 32; idx += 256) {
        int g = idx / 32, o = idx % 32;
        float s = b2[o];
        for (int k = 0; k < 16; k++) s += h1[g][k] * W2[k * 32 + o];
        h2[g][o] = s > 0.f ? s : 0.f;
    }
    __syncthreads();
    for (int idx = tid; idx < GG * 5; idx += 256) {
        int g = idx / 5, o = idx % 5;
        float s = b3[o];
        for (int k = 0; k < 32; k++) s += h2[g][k] * W3[k * 5 + o];
        out[idx] = s;
    }
}

// ---------------- launch ----------------
extern "C" void kernel_launch(void* const* d_in, const int* in_sizes, int n_in,
                              void* d_out, int out_size) {
    const float* x = (const float*)d_in[0];
    const int* ei = (const int*)d_in[1];
    const int* batch = (const int*)d_in[2];
    const float* Wl = (const float*)d_in[3];
    const float* bl = (const float*)d_in[4];
    const float* Wr = (const float*)d_in[5];
    const float* br = (const float*)d_in[6];
    const float* att = (const float*)d_in[7];
    const float* Wres = (const float*)d_in[8];
    const float* bias_attn = (const float*)d_in[9];
    const float* W_lin = (const float*)d_in[10];
    const float* b_lin = (const float*)d_in[11];
    const float* W1 = (const float*)d_in[12];
    const float* b1 = (const float*)d_in[13];
    const float* W2 = (const float*)d_in[14];
    const float* b2 = (const float*)d_in[15];
    const float* W3 = (const float*)d_in[16];
    const float* b3 = (const float*)d_in[17];
    float* out = (float*)d_out;

    // CSR build
    init_k<<<(NN + 255) / 256, 256>>>();
    deg_k<<<(EE + 255) / 256, 256>>>(ei);
    scan_k<<<1, 1024>>>();
    adj_k<<<(EE + 255) / 256, 256>>>(ei);

    // dense transforms (bf16 tensor cores, fp32 accumulate)
    dim3 blk(256);
    dim3 g1(HCD / 128, (NN + 127) / 128);
    gemm_tc_k<<<g1, blk>>>(x, 0, Wl, bl, NN, IND, HCD, 0);            // xl -> bf16
    gemm_tc_k<<<g1, blk>>>(x, 0, Wr, br, NN, IND, HCD, 1);            // xr -> bf16
    gemm_tc_k<<<g1, blk>>>(x, 0, Wres, bias_attn, NN, IND, HCD, 2);   // residual -> fp32

    // fused GATv2 attention
    node_attn_k<<<NN, 256>>>(ei, att);

    // Linear + ELU (A = g_out fp32, converted in-loader)
    dim3 g2(CC / 128, (NN + 127) / 128);
    gemm_tc_k<<<g2, blk>>>(nullptr, 1, W_lin, b_lin, NN, HCD, CC, 3);

    // pool + head
    pool_k<<<GG, 256>>>(batch);
    head_k<<<1, 256>>>(W1, b1, W2, b2, W3, b3, out);
}